// round 1
// baseline (speedup 1.0000x reference)
#include <cuda_runtime.h>
#include <math.h>

// Problem constants
#define DDIM 1024
#define NH   16
#define HP   64
#define BB   2
#define NQ   2048
#define NK   2048

// Scratch (allocation-free: __device__ globals)
__device__ float g_q [BB * NQ * DDIM];
__device__ float g_k [BB * NK * DDIM];
__device__ float g_v [BB * NK * DDIM];
__device__ float g_ao[BB * NQ * DDIM];

// ---------------------------------------------------------------------------
// GEMM:  C[r, c] = sum_k A[r, k] * W[c, k] + bias[c]   (torch Linear: A @ W^T + b)
// A: [R x 1024] row-major, W: [1024 x 1024] row-major, R = 4096.
// Tiles: 128x128x8, 256 threads, 8x8 micro-tile.
// ---------------------------------------------------------------------------
__global__ __launch_bounds__(256)
void gemm_bias_kernel(const float* __restrict__ A,
                      const float* __restrict__ W,
                      const float* __restrict__ bias,
                      float* __restrict__ C) {
    __shared__ float As[8][132];
    __shared__ float Bs[8][132];
    const int tid  = threadIdx.x;
    const int row0 = blockIdx.y * 128;
    const int col0 = blockIdx.x * 128;
    const int lr = tid >> 1;          // 0..127
    const int lc = (tid & 1) << 2;    // 0 or 4
    const int tx = tid & 15, ty = tid >> 4;
    const int rb = ty << 3, cb = tx << 3;

    float acc[8][8];
#pragma unroll
    for (int i = 0; i < 8; i++)
#pragma unroll
        for (int j = 0; j < 8; j++) acc[i][j] = 0.f;

    const float* Ap = A + (size_t)(row0 + lr) * DDIM + lc;
    const float* Wp = W + (size_t)(col0 + lr) * DDIM + lc;

    for (int kb = 0; kb < DDIM; kb += 8) {
        float4 a4 = *(const float4*)(Ap + kb);
        float4 b4 = *(const float4*)(Wp + kb);
        As[lc + 0][lr] = a4.x; As[lc + 1][lr] = a4.y;
        As[lc + 2][lr] = a4.z; As[lc + 3][lr] = a4.w;
        Bs[lc + 0][lr] = b4.x; Bs[lc + 1][lr] = b4.y;
        Bs[lc + 2][lr] = b4.z; Bs[lc + 3][lr] = b4.w;
        __syncthreads();
#pragma unroll
        for (int k = 0; k < 8; k++) {
            float ar[8], br[8];
            *(float4*)&ar[0] = *(const float4*)&As[k][rb];
            *(float4*)&ar[4] = *(const float4*)&As[k][rb + 4];
            *(float4*)&br[0] = *(const float4*)&Bs[k][cb];
            *(float4*)&br[4] = *(const float4*)&Bs[k][cb + 4];
#pragma unroll
            for (int i = 0; i < 8; i++)
#pragma unroll
                for (int j = 0; j < 8; j++)
                    acc[i][j] = fmaf(ar[i], br[j], acc[i][j]);
        }
        __syncthreads();
    }

    float4 bb0 = *(const float4*)&bias[col0 + cb];
    float4 bb1 = *(const float4*)&bias[col0 + cb + 4];
#pragma unroll
    for (int i = 0; i < 8; i++) {
        float4 o0, o1;
        o0.x = acc[i][0] + bb0.x; o0.y = acc[i][1] + bb0.y;
        o0.z = acc[i][2] + bb0.z; o0.w = acc[i][3] + bb0.w;
        o1.x = acc[i][4] + bb1.x; o1.y = acc[i][5] + bb1.y;
        o1.z = acc[i][6] + bb1.z; o1.w = acc[i][7] + bb1.w;
        float* cp = C + (size_t)(row0 + rb + i) * DDIM + col0 + cb;
        *(float4*)cp       = o0;
        *(float4*)(cp + 4) = o1;
    }
}

// ---------------------------------------------------------------------------
// Flash attention, fp32. One CTA = (b, h, 64-query block). 256 threads.
// Smem (dynamic, 50944 B):
//   Qt [64p][64q]       : Q tile, p-major, pre-scaled by 1/8
//   KS                  : K tile Kt[64p][64k] (stride 64) during S-GEMM,
//                         then reused as S^T [64k][.. ] with stride 68
//   Vs [64k][64p]       : V tile natural layout
//   mi/li/al [64]       : online-softmax row state
// ---------------------------------------------------------------------------
__global__ __launch_bounds__(256)
void attn_kernel(const float* __restrict__ q,
                 const float* __restrict__ k,
                 const float* __restrict__ v,
                 float* __restrict__ o) {
    extern __shared__ float sm[];
    float* Qt = sm;               // 64*64
    float* KS = Qt + 64 * 64;     // 64*68 (Kt uses stride 64, St uses stride 68)
    float* Vs = KS + 64 * 68;     // 64*64
    float* mi = Vs + 64 * 64;     // 64
    float* li = mi + 64;          // 64
    float* al = li + 64;          // 64

    const int tid = threadIdx.x;
    const int q0  = blockIdx.x * 64;
    const int h   = blockIdx.y;
    const int b   = blockIdx.z;
    const float scale = 0.125f;   // 1/sqrt(64)

    const float* qp = q + ((size_t)b * NQ) * DDIM + h * HP;
    const float* kp = k + ((size_t)b * NK) * DDIM + h * HP;
    const float* vp = v + ((size_t)b * NK) * DDIM + h * HP;

    // Load Q tile transposed, pre-scaled
#pragma unroll
    for (int t = 0; t < 4; t++) {
        int idx = tid + t * 256;
        int r = idx >> 4;
        int c = (idx & 15) << 2;
        float4 x = *(const float4*)(qp + (size_t)(q0 + r) * DDIM + c);
        Qt[(c + 0) * 64 + r] = x.x * scale;
        Qt[(c + 1) * 64 + r] = x.y * scale;
        Qt[(c + 2) * 64 + r] = x.z * scale;
        Qt[(c + 3) * 64 + r] = x.w * scale;
    }
    if (tid < 64) { mi[tid] = -3.0e38f; li[tid] = 0.f; }

    const int tx = tid & 15, ty = tid >> 4;
    const int rb = ty << 2, cb = tx << 2;   // 4x4 micro-tile
    float oacc[4][4];
#pragma unroll
    for (int i = 0; i < 4; i++)
#pragma unroll
        for (int j = 0; j < 4; j++) oacc[i][j] = 0.f;

    for (int k0 = 0; k0 < NK; k0 += 64) {
        __syncthreads();   // prior-iter consumers done; Q visible on first iter

        // Load K (transposed) and V (natural)
#pragma unroll
        for (int t = 0; t < 4; t++) {
            int idx = tid + t * 256;
            int r = idx >> 4;
            int c = (idx & 15) << 2;
            float4 kx = *(const float4*)(kp + (size_t)(k0 + r) * DDIM + c);
            KS[(c + 0) * 64 + r] = kx.x;
            KS[(c + 1) * 64 + r] = kx.y;
            KS[(c + 2) * 64 + r] = kx.z;
            KS[(c + 3) * 64 + r] = kx.w;
            float4 vx = *(const float4*)(vp + (size_t)(k0 + r) * DDIM + c);
            *(float4*)&Vs[r * 64 + c] = vx;
        }
        __syncthreads();

        // S = (Q*scale) @ K^T  -> sacc (rows = queries rb.., cols = keys cb..)
        float sacc[4][4];
#pragma unroll
        for (int i = 0; i < 4; i++)
#pragma unroll
            for (int j = 0; j < 4; j++) sacc[i][j] = 0.f;
#pragma unroll 8
        for (int p = 0; p < 64; p++) {
            float a[4], br[4];
            *(float4*)a  = *(const float4*)&Qt[p * 64 + rb];
            *(float4*)br = *(const float4*)&KS[p * 64 + cb];
#pragma unroll
            for (int i = 0; i < 4; i++)
#pragma unroll
                for (int j = 0; j < 4; j++)
                    sacc[i][j] = fmaf(a[i], br[j], sacc[i][j]);
        }
        __syncthreads();   // everyone done reading Kt

        // Store S transposed into KS with stride 68: St[key][query]
#pragma unroll
        for (int j = 0; j < 4; j++)
#pragma unroll
            for (int i = 0; i < 4; i++)
                KS[(cb + j) * 68 + rb + i] = sacc[i][j];
        __syncthreads();

        // Online softmax: thread r < 64 owns query row r (conflict-free column reads)
        if (tid < 64) {
            int r = tid;
            float m_old = mi[r];
            float m = m_old;
#pragma unroll 8
            for (int kk = 0; kk < 64; kk++) m = fmaxf(m, KS[kk * 68 + r]);
            float a = __expf(m_old - m);
            float s = 0.f;
#pragma unroll 8
            for (int kk = 0; kk < 64; kk++) {
                float e = __expf(KS[kk * 68 + r] - m);
                KS[kk * 68 + r] = e;
                s += e;
            }
            li[r] = li[r] * a + s;
            mi[r] = m;
            al[r] = a;
        }
        __syncthreads();

        // Rescale running output, then O += P @ V
        float a0 = al[rb], a1 = al[rb + 1], a2 = al[rb + 2], a3 = al[rb + 3];
#pragma unroll
        for (int j = 0; j < 4; j++) {
            oacc[0][j] *= a0; oacc[1][j] *= a1;
            oacc[2][j] *= a2; oacc[3][j] *= a3;
        }
#pragma unroll 8
        for (int kk = 0; kk < 64; kk++) {
            float pr[4], vr[4];
            *(float4*)pr = *(const float4*)&KS[kk * 68 + rb];   // 68*4 bytes = 16B-aligned rows
            *(float4*)vr = *(const float4*)&Vs[kk * 64 + cb];
#pragma unroll
            for (int i = 0; i < 4; i++)
#pragma unroll
                for (int j = 0; j < 4; j++)
                    oacc[i][j] = fmaf(pr[i], vr[j], oacc[i][j]);
        }
    }
    __syncthreads();

    // Normalize and write [b, n, h*64 + p]
#pragma unroll
    for (int i = 0; i < 4; i++) {
        float inv = 1.f / li[rb + i];
        float4 w;
        w.x = oacc[i][0] * inv; w.y = oacc[i][1] * inv;
        w.z = oacc[i][2] * inv; w.w = oacc[i][3] * inv;
        float* op = o + ((size_t)b * NQ + q0 + rb + i) * DDIM + h * HP + cb;
        *(float4*)op = w;
    }
}

// ---------------------------------------------------------------------------
// Launch
// ---------------------------------------------------------------------------
extern "C" void kernel_launch(void* const* d_in, const int* in_sizes, int n_in,
                              void* d_out, int out_size) {
    (void)in_sizes; (void)n_in; (void)out_size;
    const float* queries = (const float*)d_in[0];
    const float* keys    = (const float*)d_in[1];
    const float* values  = (const float*)d_in[2];
    const float* Wq = (const float*)d_in[3];  const float* bq = (const float*)d_in[4];
    const float* Wk = (const float*)d_in[5];  const float* bk = (const float*)d_in[6];
    const float* Wv = (const float*)d_in[7];  const float* bv = (const float*)d_in[8];
    const float* Wo = (const float*)d_in[9];  const float* bo = (const float*)d_in[10];
    float* out = (float*)d_out;

    float *qp, *kp, *vp, *ap;
    cudaGetSymbolAddress((void**)&qp, g_q);
    cudaGetSymbolAddress((void**)&kp, g_k);
    cudaGetSymbolAddress((void**)&vp, g_v);
    cudaGetSymbolAddress((void**)&ap, g_ao);

    const int smem_bytes = (64 * 64 + 64 * 68 + 64 * 64 + 3 * 64) * (int)sizeof(float); // 50944
    cudaFuncSetAttribute(attn_kernel, cudaFuncAttributeMaxDynamicSharedMemorySize, smem_bytes);

    dim3 gemm_grid(DDIM / 128, (BB * NQ) / 128);   // (8, 32)

    gemm_bias_kernel<<<gemm_grid, 256>>>(queries, Wq, bq, qp);
    gemm_bias_kernel<<<gemm_grid, 256>>>(keys,    Wk, bk, kp);
    gemm_bias_kernel<<<gemm_grid, 256>>>(values,  Wv, bv, vp);

    attn_kernel<<<dim3(NQ / 64, NH, BB), 256, smem_bytes>>>(qp, kp, vp, ap);

    gemm_bias_kernel<<<gemm_grid, 256>>>(ap, Wo, bo, out);
}

// round 3
// speedup vs baseline: 2.9525x; 2.9525x over previous
#include <cuda_runtime.h>
#include <cstdint>
#include <math.h>

// Problem constants
#define DDIM 1024
#define NH   16
#define HP   64
#define BB   2
#define NQ   2048
#define NK   2048

// Scratch (allocation-free: __device__ globals)
__device__ float g_q [BB * NQ * DDIM];
__device__ float g_k [BB * NK * DDIM];
__device__ float g_v [BB * NK * DDIM];
__device__ float g_ao[BB * NQ * DDIM];

// ---------------------------------------------------------------------------
// Portable tensor-core helpers (sm_80+ PTX; works at compute_100 base target)
// ---------------------------------------------------------------------------
__device__ __forceinline__ uint32_t f2tf32(float x) {
    uint32_t r;
    asm("cvt.rna.tf32.f32 %0, %1;" : "=r"(r) : "f"(x));
    return r;
}

// D (f32 4) += A (tf32 m16k8, 4 regs) * B (tf32 k8n8, 2 regs)
__device__ __forceinline__ void mma_tf32(float* d, const uint32_t* a, const uint32_t* b) {
    asm volatile(
        "mma.sync.aligned.m16n8k8.row.col.f32.tf32.tf32.f32 "
        "{%0,%1,%2,%3}, {%4,%5,%6,%7}, {%8,%9}, {%0,%1,%2,%3};"
        : "+f"(d[0]), "+f"(d[1]), "+f"(d[2]), "+f"(d[3])
        : "r"(a[0]), "r"(a[1]), "r"(a[2]), "r"(a[3]), "r"(b[0]), "r"(b[1]));
}

// ---------------------------------------------------------------------------
// tf32 mma.sync GEMM: C[r,c] = sum_k A[r,k]*W[c,k] + bias[c]
// A: [4096 x 1024] rm, W: [1024 x 1024] rm.
// CTA tile 128x128, 8 warps of 64x32 (wm = wid&1 rows, wn = wid>>1 cols).
// K-chunks of 32, double-buffered smem (stride 36 words, conflict-free frags).
// ---------------------------------------------------------------------------
#define GS 36
#define GEMM_SMEM_FLOATS (2 * (128 * GS) * 2)     // 2 bufs x (A+B) = 18432 floats
#define GEMM_SMEM_BYTES  (GEMM_SMEM_FLOATS * 4)   // 73728

__global__ __launch_bounds__(256)
void gemm_mma_kernel(const float* __restrict__ A,
                     const float* __restrict__ W,
                     const float* __restrict__ bias,
                     float* __restrict__ C) {
    extern __shared__ uint32_t gsm[];
    uint32_t* sA[2] = { gsm,               gsm + 2 * 128 * GS };
    uint32_t* sB[2] = { gsm + 128 * GS,    gsm + 3 * 128 * GS };

    const int tid  = threadIdx.x;
    const int wid  = tid >> 5;
    const int lane = tid & 31;
    const int gid  = lane >> 2;
    const int tig  = lane & 3;
    const int wm   = wid & 1;        // 0..1 -> 64-row half
    const int wn   = wid >> 1;       // 0..3 -> 32-col quarter
    const int col0 = blockIdx.x * 128;
    const int row0 = blockIdx.y * 128;

    const int ldr = tid >> 3;              // 0..31 rows per pass (x4 passes = 128)
    const int ldc = (tid & 7) << 2;        // 0,4,...,28

    float acc[4][4][4];                    // [mt][nt][frag]
#pragma unroll
    for (int mt = 0; mt < 4; mt++)
#pragma unroll
        for (int nt = 0; nt < 4; nt++)
#pragma unroll
            for (int f = 0; f < 4; f++) acc[mt][nt][f] = 0.f;

    float ra[16], rb[16];

    // Preload chunk 0 into regs, then STS buf0
#pragma unroll
    for (int t = 0; t < 4; t++) {
        int r = ldr + t * 32;
        *(float4*)&ra[t * 4] = *(const float4*)(A + (size_t)(row0 + r) * DDIM + ldc);
        *(float4*)&rb[t * 4] = *(const float4*)(W + (size_t)(col0 + r) * DDIM + ldc);
    }
#pragma unroll
    for (int t = 0; t < 4; t++) {
        int r = ldr + t * 32;
#pragma unroll
        for (int u = 0; u < 4; u++) {
            sA[0][r * GS + ldc + u] = f2tf32(ra[t * 4 + u]);
            sB[0][r * GS + ldc + u] = f2tf32(rb[t * 4 + u]);
        }
    }
    __syncthreads();

    for (int i = 0; i < 32; i++) {
        const int cur = i & 1;
        if (i < 31) {
            const int k0 = (i + 1) * 32;
#pragma unroll
            for (int t = 0; t < 4; t++) {
                int r = ldr + t * 32;
                *(float4*)&ra[t * 4] = *(const float4*)(A + (size_t)(row0 + r) * DDIM + k0 + ldc);
                *(float4*)&rb[t * 4] = *(const float4*)(W + (size_t)(col0 + r) * DDIM + k0 + ldc);
            }
        }
        const uint32_t* cA = sA[cur];
        const uint32_t* cB = sB[cur];
#pragma unroll
        for (int kt = 0; kt < 4; kt++) {
            uint32_t af[4][4], bf[4][2];
#pragma unroll
            for (int mt = 0; mt < 4; mt++) {
                int rbase = wm * 64 + mt * 16 + gid;
                af[mt][0] = cA[rbase * GS + kt * 8 + tig];
                af[mt][1] = cA[(rbase + 8) * GS + kt * 8 + tig];
                af[mt][2] = cA[rbase * GS + kt * 8 + tig + 4];
                af[mt][3] = cA[(rbase + 8) * GS + kt * 8 + tig + 4];
            }
#pragma unroll
            for (int nt = 0; nt < 4; nt++) {
                int nbase = wn * 32 + nt * 8 + gid;
                bf[nt][0] = cB[nbase * GS + kt * 8 + tig];
                bf[nt][1] = cB[nbase * GS + kt * 8 + tig + 4];
            }
#pragma unroll
            for (int mt = 0; mt < 4; mt++)
#pragma unroll
                for (int nt = 0; nt < 4; nt++)
                    mma_tf32(acc[mt][nt], af[mt], bf[nt]);
        }
        __syncthreads();
        if (i < 31) {
            const int nxt = cur ^ 1;
#pragma unroll
            for (int t = 0; t < 4; t++) {
                int r = ldr + t * 32;
#pragma unroll
                for (int u = 0; u < 4; u++) {
                    sA[nxt][r * GS + ldc + u] = f2tf32(ra[t * 4 + u]);
                    sB[nxt][r * GS + ldc + u] = f2tf32(rb[t * 4 + u]);
                }
            }
            __syncthreads();
        }
    }

    // Epilogue with bias
#pragma unroll
    for (int mt = 0; mt < 4; mt++) {
        int r = row0 + wm * 64 + mt * 16 + gid;
#pragma unroll
        for (int nt = 0; nt < 4; nt++) {
            int c = col0 + wn * 32 + nt * 8 + tig * 2;
            float b0 = bias[c], b1 = bias[c + 1];
            float2 o0 = make_float2(acc[mt][nt][0] + b0, acc[mt][nt][1] + b1);
            float2 o1 = make_float2(acc[mt][nt][2] + b0, acc[mt][nt][3] + b1);
            *(float2*)(C + (size_t)r * DDIM + c)       = o0;
            *(float2*)(C + (size_t)(r + 8) * DDIM + c) = o1;
        }
    }
}

// ---------------------------------------------------------------------------
// Flash attention with tf32 mma.sync.
// CTA = (128 queries, head, batch). 8 warps; warp w owns query rows w*16..+15.
// smem: QP [128][68]  (Q tf32, later reused warp-private for P)
//       Ks [64][68]   (K tf32)
//       Vs [64][72]   (V tf32)
// ---------------------------------------------------------------------------
#define QS 68
#define VS 72
#define ATTN_SMEM_FLOATS (128 * QS + 64 * QS + 64 * VS)   // 17664
#define ATTN_SMEM_BYTES  (ATTN_SMEM_FLOATS * 4)           // 70656

__global__ __launch_bounds__(256)
void attn_mma_kernel(const float* __restrict__ q,
                     const float* __restrict__ k,
                     const float* __restrict__ v,
                     float* __restrict__ o) {
    extern __shared__ uint32_t asm_[];
    uint32_t* QP = asm_;                 // 128 x 68
    uint32_t* Ks = QP + 128 * QS;        // 64 x 68
    uint32_t* Vs = Ks + 64 * QS;         // 64 x 72

    const int tid  = threadIdx.x;
    const int wid  = tid >> 5;
    const int lane = tid & 31;
    const int gid  = lane >> 2;
    const int tig  = lane & 3;
    const int wq   = wid * 16;           // warp's query-row base within tile

    const int q0 = blockIdx.x * 128;
    const int h  = blockIdx.y;
    const int b  = blockIdx.z;
    const float scale = 0.125f;          // 1/sqrt(64)

    const float* qp = q + ((size_t)b * NQ) * DDIM + h * HP;
    const float* kp = k + ((size_t)b * NK) * DDIM + h * HP;
    const float* vp = v + ((size_t)b * NK) * DDIM + h * HP;

    // ---- Load Q tile (scaled, tf32) ----
    {
        const int r = tid >> 4;               // 0..15 (+16 per pass)
        const int c = (tid & 15) << 2;        // 0,4,...,60
#pragma unroll
        for (int t = 0; t < 8; t++) {
            int rr = r + t * 16;
            float4 x = *(const float4*)(qp + (size_t)(q0 + rr) * DDIM + c);
            QP[rr * QS + c + 0] = f2tf32(x.x * scale);
            QP[rr * QS + c + 1] = f2tf32(x.y * scale);
            QP[rr * QS + c + 2] = f2tf32(x.z * scale);
            QP[rr * QS + c + 3] = f2tf32(x.w * scale);
        }
    }
    __syncthreads();

    // ---- Extract Q fragments (warp-private rows) ----
    uint32_t qf[8][4];
#pragma unroll
    for (int kt = 0; kt < 8; kt++) {
        int rbase = (wq + gid) * QS + kt * 8 + tig;
        qf[kt][0] = QP[rbase];
        qf[kt][1] = QP[rbase + 8 * QS];
        qf[kt][2] = QP[rbase + 4];
        qf[kt][3] = QP[rbase + 8 * QS + 4];
    }
    // From here QP rows are warp-private (reused for P).

    float oacc[8][4];
#pragma unroll
    for (int nt = 0; nt < 8; nt++)
#pragma unroll
        for (int f = 0; f < 4; f++) oacc[nt][f] = 0.f;
    float m0 = -3.0e38f, m1 = -3.0e38f, l0 = 0.f, l1 = 0.f;

    const int kr = tid >> 4;              // K/V loader row 0..15
    const int kc = (tid & 15) << 2;

    for (int k0 = 0; k0 < NK; k0 += 64) {
        __syncthreads();   // prior iteration's K/V consumers done
#pragma unroll
        for (int t = 0; t < 4; t++) {
            int rr = kr + t * 16;
            float4 kx = *(const float4*)(kp + (size_t)(k0 + rr) * DDIM + kc);
            Ks[rr * QS + kc + 0] = f2tf32(kx.x);
            Ks[rr * QS + kc + 1] = f2tf32(kx.y);
            Ks[rr * QS + kc + 2] = f2tf32(kx.z);
            Ks[rr * QS + kc + 3] = f2tf32(kx.w);
            float4 vx = *(const float4*)(vp + (size_t)(k0 + rr) * DDIM + kc);
            Vs[rr * VS + kc + 0] = f2tf32(vx.x);
            Vs[rr * VS + kc + 1] = f2tf32(vx.y);
            Vs[rr * VS + kc + 2] = f2tf32(vx.z);
            Vs[rr * VS + kc + 3] = f2tf32(vx.w);
        }
        __syncthreads();

        // ---- S = Q @ K^T : 8 ntiles (keys), 8 k-steps (p-dim) ----
        float sacc[8][4];
#pragma unroll
        for (int nt = 0; nt < 8; nt++)
#pragma unroll
            for (int f = 0; f < 4; f++) sacc[nt][f] = 0.f;
#pragma unroll
        for (int kt = 0; kt < 8; kt++) {
#pragma unroll
            for (int nt = 0; nt < 8; nt++) {
                uint32_t bf[2];
                int nbase = (nt * 8 + gid) * QS + kt * 8 + tig;
                bf[0] = Ks[nbase];
                bf[1] = Ks[nbase + 4];
                mma_tf32(sacc[nt], qf[kt], bf);
            }
        }

        // ---- Online softmax (in-register, intra-quad shuffles) ----
        float v0 = -3.0e38f, v1 = -3.0e38f;
#pragma unroll
        for (int nt = 0; nt < 8; nt++) {
            v0 = fmaxf(v0, fmaxf(sacc[nt][0], sacc[nt][1]));
            v1 = fmaxf(v1, fmaxf(sacc[nt][2], sacc[nt][3]));
        }
        v0 = fmaxf(v0, __shfl_xor_sync(0xffffffff, v0, 1));
        v0 = fmaxf(v0, __shfl_xor_sync(0xffffffff, v0, 2));
        v1 = fmaxf(v1, __shfl_xor_sync(0xffffffff, v1, 1));
        v1 = fmaxf(v1, __shfl_xor_sync(0xffffffff, v1, 2));
        float nm0 = fmaxf(m0, v0), nm1 = fmaxf(m1, v1);
        float a0 = __expf(m0 - nm0), a1 = __expf(m1 - nm1);
        float s0 = 0.f, s1 = 0.f;
#pragma unroll
        for (int nt = 0; nt < 8; nt++) {
            sacc[nt][0] = __expf(sacc[nt][0] - nm0);
            sacc[nt][1] = __expf(sacc[nt][1] - nm0);
            sacc[nt][2] = __expf(sacc[nt][2] - nm1);
            sacc[nt][3] = __expf(sacc[nt][3] - nm1);
            s0 += sacc[nt][0] + sacc[nt][1];
            s1 += sacc[nt][2] + sacc[nt][3];
        }
        s0 += __shfl_xor_sync(0xffffffff, s0, 1);
        s0 += __shfl_xor_sync(0xffffffff, s0, 2);
        s1 += __shfl_xor_sync(0xffffffff, s1, 1);
        s1 += __shfl_xor_sync(0xffffffff, s1, 2);
        l0 = l0 * a0 + s0;  l1 = l1 * a1 + s1;
        m0 = nm0;  m1 = nm1;

        // Rescale running O
#pragma unroll
        for (int nt = 0; nt < 8; nt++) {
            oacc[nt][0] *= a0; oacc[nt][1] *= a0;
            oacc[nt][2] *= a1; oacc[nt][3] *= a1;
        }

        // ---- Stage P (warp-private rows of QP) ----
#pragma unroll
        for (int nt = 0; nt < 8; nt++) {
            int base0 = (wq + gid) * QS + nt * 8 + tig * 2;
            QP[base0]              = f2tf32(sacc[nt][0]);
            QP[base0 + 1]          = f2tf32(sacc[nt][1]);
            QP[base0 + 8 * QS]     = f2tf32(sacc[nt][2]);
            QP[base0 + 8 * QS + 1] = f2tf32(sacc[nt][3]);
        }
        __syncwarp();

        // ---- O += P @ V : k over 64 keys, 8 ntiles over p ----
#pragma unroll
        for (int kt = 0; kt < 8; kt++) {
            uint32_t af[4];
            int abase = (wq + gid) * QS + kt * 8 + tig;
            af[0] = QP[abase];
            af[1] = QP[abase + 8 * QS];
            af[2] = QP[abase + 4];
            af[3] = QP[abase + 8 * QS + 4];
#pragma unroll
            for (int nt = 0; nt < 8; nt++) {
                uint32_t bf[2];
                int bbase = (kt * 8 + tig) * VS + nt * 8 + gid;
                bf[0] = Vs[bbase];
                bf[1] = Vs[bbase + 4 * VS];
                mma_tf32(oacc[nt], af, bf);
            }
        }
        __syncwarp();
    }

    // ---- Normalize and write out ----
    float inv0 = 1.f / l0, inv1 = 1.f / l1;
    const int row = q0 + wq + gid;
#pragma unroll
    for (int nt = 0; nt < 8; nt++) {
        int c = h * HP + nt * 8 + tig * 2;
        float2 o0 = make_float2(oacc[nt][0] * inv0, oacc[nt][1] * inv0);
        float2 o1 = make_float2(oacc[nt][2] * inv1, oacc[nt][3] * inv1);
        *(float2*)(o + ((size_t)b * NQ + row) * DDIM + c)     = o0;
        *(float2*)(o + ((size_t)b * NQ + row + 8) * DDIM + c) = o1;
    }
}

// ---------------------------------------------------------------------------
// Launch
// ---------------------------------------------------------------------------
extern "C" void kernel_launch(void* const* d_in, const int* in_sizes, int n_in,
                              void* d_out, int out_size) {
    (void)in_sizes; (void)n_in; (void)out_size;
    const float* queries = (const float*)d_in[0];
    const float* keys    = (const float*)d_in[1];
    const float* values  = (const float*)d_in[2];
    const float* Wq = (const float*)d_in[3];  const float* bq = (const float*)d_in[4];
    const float* Wk = (const float*)d_in[5];  const float* bk = (const float*)d_in[6];
    const float* Wv = (const float*)d_in[7];  const float* bv = (const float*)d_in[8];
    const float* Wo = (const float*)d_in[9];  const float* bo = (const float*)d_in[10];
    float* out = (float*)d_out;

    float *qp, *kp, *vp, *ap;
    cudaGetSymbolAddress((void**)&qp, g_q);
    cudaGetSymbolAddress((void**)&kp, g_k);
    cudaGetSymbolAddress((void**)&vp, g_v);
    cudaGetSymbolAddress((void**)&ap, g_ao);

    cudaFuncSetAttribute(gemm_mma_kernel,
                         cudaFuncAttributeMaxDynamicSharedMemorySize, GEMM_SMEM_BYTES);
    cudaFuncSetAttribute(attn_mma_kernel,
                         cudaFuncAttributeMaxDynamicSharedMemorySize, ATTN_SMEM_BYTES);

    dim3 gemm_grid(DDIM / 128, (BB * NQ) / 128);   // (8, 32)

    gemm_mma_kernel<<<gemm_grid, 256, GEMM_SMEM_BYTES>>>(queries, Wq, bq, qp);
    gemm_mma_kernel<<<gemm_grid, 256, GEMM_SMEM_BYTES>>>(keys,    Wk, bk, kp);
    gemm_mma_kernel<<<gemm_grid, 256, GEMM_SMEM_BYTES>>>(values,  Wv, bv, vp);

    attn_mma_kernel<<<dim3(NQ / 128, NH, BB), 256, ATTN_SMEM_BYTES>>>(qp, kp, vp, ap);

    gemm_mma_kernel<<<gemm_grid, 256, GEMM_SMEM_BYTES>>>(ap, Wo, bo, out);
}